// round 14
// baseline (speedup 1.0000x reference)
#include <cuda_runtime.h>
#include <cuda_bf16.h>
#include <cstdint>
#include <math.h>

#define N_TOK 16384
#define D     768
#define DC    64
#define KCODES 8192

// ---------------- scratch (device globals: no runtime allocation) ----------------
__device__ float g_H[N_TOK * D];                 // tanh(Z@W1+b1), 48 MB
__device__ float g_Ze[N_TOK * DC];               // normalized encoder output, 4 MB
__device__ unsigned long long g_best[N_TOK];     // packed (mapped_sim<<32)|(8191-idx)
__device__ float g_loss_part[N_TOK / 16];        // per-block loss partials

// bf16 3-way exact splits (x = s0 + s1 + s2 + O(2^-27 x))
__device__ __align__(16) __nv_bfloat16 g_ZeSp0[N_TOK * DC];
__device__ __align__(16) __nv_bfloat16 g_ZeSp1[N_TOK * DC];
__device__ __align__(16) __nv_bfloat16 g_ZeSp2[N_TOK * DC];
__device__ __align__(16) __nv_bfloat16 g_ESp0[KCODES * DC];
__device__ __align__(16) __nv_bfloat16 g_ESp1[KCODES * DC];
__device__ __align__(16) __nv_bfloat16 g_ESp2[KCODES * DC];
// splits for gemm1: Z [N_TOK x D], W1 transposed [n][k] (n,k in 0..767)
__device__ __align__(16) __nv_bfloat16 g_ZSp0[N_TOK * D];
__device__ __align__(16) __nv_bfloat16 g_ZSp1[N_TOK * D];
__device__ __align__(16) __nv_bfloat16 g_ZSp2[N_TOK * D];
__device__ __align__(16) __nv_bfloat16 g_W1TSp0[D * D];
__device__ __align__(16) __nv_bfloat16 g_W1TSp1[D * D];
__device__ __align__(16) __nv_bfloat16 g_W1TSp2[D * D];

// monotonic float->uint mapping (total order preserving)
__device__ __forceinline__ unsigned int fmap(float f) {
    unsigned int u = __float_as_uint(f);
    return (u & 0x80000000u) ? ~u : (u | 0x80000000u);
}

__device__ __forceinline__ uint32_t smem_u32(const void* p) {
    uint32_t a;
    asm("{ .reg .u64 t; cvta.to.shared.u64 t, %1; cvt.u32.u64 %0, t; }"
        : "=r"(a) : "l"(p));
    return a;
}

#define LDSM4(r0, r1, r2, r3, addr) \
    asm volatile("ldmatrix.sync.aligned.m8n8.x4.shared.b16 {%0,%1,%2,%3}, [%4];" \
                 : "=r"(r0), "=r"(r1), "=r"(r2), "=r"(r3) : "r"(addr))

#define MMA16816(c, a, b0, b1) \
    asm volatile("mma.sync.aligned.m16n8k16.row.col.f32.bf16.bf16.f32 " \
                 "{%0,%1,%2,%3}, {%4,%5,%6,%7}, {%8,%9}, {%0,%1,%2,%3};" \
                 : "+f"((c)[0]), "+f"((c)[1]), "+f"((c)[2]), "+f"((c)[3]) \
                 : "r"((a)[0]), "r"((a)[1]), "r"((a)[2]), "r"((a)[3]), \
                   "r"(b0), "r"(b1))

__device__ __forceinline__ void split3(float x, __nv_bfloat16& s0,
                                       __nv_bfloat16& s1, __nv_bfloat16& s2) {
    s0 = __float2bfloat16(x);
    float r1 = x - __bfloat162float(s0);
    s1 = __float2bfloat16(r1);
    s2 = __float2bfloat16(r1 - __bfloat162float(s1));
}

// ---------------- kernel 0: split Z, W1^T, emb into bf16x3 planes ----------------
#define NZ   (N_TOK * D)
#define NW1  (D * D)
#define NE   (KCODES * DC)
__global__ void k_split_in(const float* __restrict__ Z,
                           const float* __restrict__ W1,
                           const float* __restrict__ emb)
{
    int i = blockIdx.x * 256 + threadIdx.x;
    if (i < NZ) {
        split3(Z[i], g_ZSp0[i], g_ZSp1[i], g_ZSp2[i]);
    } else if (i < NZ + NW1) {
        int j = i - NZ;                        // j = n*768 + k  (coalesced writes)
        int n = j / D, k = j - n * D;
        split3(W1[(size_t)k * D + n], g_W1TSp0[j], g_W1TSp1[j], g_W1TSp2[j]);
    } else if (i < NZ + NW1 + NE) {
        int j = i - NZ - NW1;
        split3(emb[j], g_ESp0[j], g_ESp1[j], g_ESp2[j]);
    }
}

// ---------------- kernel 1: H = tanh(Z @ W1 + b1) via mma.sync bf16x6 -------------
// CTA 256 thr / 8 warps; tile 128(M) x 128(N); K-loop 12 chunks of 64.
// Warp tile 64x32 (wm = w&1, wn = w>>1). smem 96KB -> 2 CTAs/SM.
// Also zeroes loss+codex output and g_best (DRAM idle during tensor work).
#define G1_SMEM 98304
__global__ __launch_bounds__(256, 2) void k_gemm1_mma(
    const float* __restrict__ bias, float4* __restrict__ zero4)
{
    extern __shared__ char sm[];
    const uint32_t smb = smem_u32(sm);
    const int tid = threadIdx.x;
    const int lane = tid & 31, w = tid >> 5;
    const int row0 = blockIdx.y * 128;       // tokens
    const int col0 = blockIdx.x * 128;       // H columns
    const int wm = w & 1, wn = w >> 1;

    // ---- fire-and-forget zeroing of loss + one-hot output + g_best ----
    {
        const unsigned int flat = blockIdx.y * gridDim.x + blockIdx.x;   // 0..767
        const float4 z4 = make_float4(0.f, 0.f, 0.f, 0.f);
        const size_t total4 = ((size_t)N_TOK * KCODES + 1) / 4;
        const size_t stride = (size_t)768 * 256;
        for (size_t i = (size_t)flat * 256 + tid; i < total4; i += stride)
            zero4[i] = z4;
        if (flat == 0 && tid == 0)
            ((float*)zero4)[(size_t)N_TOK * KCODES] = 0.f;
        if (flat < 64) g_best[flat * 256 + tid] = 0ull;
    }

    float acc[4][4][4];
    #pragma unroll
    for (int mi = 0; mi < 4; mi++)
        #pragma unroll
        for (int ni = 0; ni < 4; ni++)
            #pragma unroll
            for (int f = 0; f < 4; f++) acc[mi][ni][f] = 0.f;

    const int l = lane & 7;
    const int sel = lane >> 3;
    const int pa[6] = {0, 0, 1, 1, 0, 2};
    const int pb[6] = {0, 1, 0, 1, 2, 0};

    const __nv_bfloat16* Ap[3] = { g_ZSp0, g_ZSp1, g_ZSp2 };
    const __nv_bfloat16* Bp[3] = { g_W1TSp0, g_W1TSp1, g_W1TSp2 };

    for (int kc0 = 0; kc0 < D; kc0 += 64) {
        // load A planes: 128 rows x 64 cols (=128B) each, swizzled chunk^=row&7
        #pragma unroll
        for (int p = 0; p < 3; p++)
            #pragma unroll
            for (int it = 0; it < 4; it++) {
                int idx = tid + it * 256;            // 0..1023 = row*8 + chunk
                int r = idx >> 3, c = idx & 7;
                uint4 v = *(const uint4*)(Ap[p] + (size_t)(row0 + r) * D + kc0 + c * 8);
                *(uint4*)(sm + p * 16384 + r * 128 + ((c ^ (r & 7)) << 4)) = v;
            }
        #pragma unroll
        for (int p = 0; p < 3; p++)
            #pragma unroll
            for (int it = 0; it < 4; it++) {
                int idx = tid + it * 256;
                int r = idx >> 3, c = idx & 7;
                uint4 v = *(const uint4*)(Bp[p] + (size_t)(col0 + r) * D + kc0 + c * 8);
                *(uint4*)(sm + 49152 + p * 16384 + r * 128 + ((c ^ (r & 7)) << 4)) = v;
            }
        __syncthreads();

        #pragma unroll
        for (int pr = 0; pr < 6; pr++) {
            const uint32_t abase = smb + pa[pr] * 16384;
            const uint32_t bbase = smb + 49152 + pb[pr] * 16384;
            #pragma unroll
            for (int k16 = 0; k16 < 4; k16++) {
                uint32_t a[4][4];
                #pragma unroll
                for (int mi = 0; mi < 4; mi++) {
                    int row = wm * 64 + mi * 16 + ((sel & 1) << 3) + l;
                    int ch  = k16 * 2 + (sel >> 1);
                    uint32_t addr = abase + row * 128 + ((ch ^ (row & 7)) << 4);
                    LDSM4(a[mi][0], a[mi][1], a[mi][2], a[mi][3], addr);
                }
                #pragma unroll
                for (int p2 = 0; p2 < 2; p2++) {
                    uint32_t b0, b1, b2, b3;
                    int nrow = wn * 32 + (p2 * 2 + (sel >> 1)) * 8 + l;
                    int ch = k16 * 2 + (sel & 1);
                    uint32_t addr = bbase + nrow * 128 + ((ch ^ (nrow & 7)) << 4);
                    LDSM4(b0, b1, b2, b3, addr);
                    #pragma unroll
                    for (int mi = 0; mi < 4; mi++) {
                        MMA16816(acc[mi][p2 * 2],     a[mi], b0, b1);
                        MMA16816(acc[mi][p2 * 2 + 1], a[mi], b2, b3);
                    }
                }
            }
        }
        __syncthreads();
    }

    // ---- epilogue: + bias, tanh, store fp32 H ----
    const int gid = lane >> 2, tig = lane & 3;
    float2 bb[4];
    #pragma unroll
    for (int ni = 0; ni < 4; ni++)
        bb[ni] = *(const float2*)&bias[col0 + wn * 32 + ni * 8 + tig * 2];
    #pragma unroll
    for (int mi = 0; mi < 4; mi++)
        #pragma unroll
        for (int half = 0; half < 2; half++) {
            int row = row0 + wm * 64 + mi * 16 + half * 8 + gid;
            #pragma unroll
            for (int ni = 0; ni < 4; ni++) {
                int col = col0 + wn * 32 + ni * 8 + tig * 2;
                float2 o;
                o.x = tanhf(acc[mi][ni][half * 2]     + bb[ni].x);
                o.y = tanhf(acc[mi][ni][half * 2 + 1] + bb[ni].y);
                *(float2*)&g_H[(size_t)row * D + col] = o;
            }
        }
}

// ---------------- kernel 2: Ze = l2norm(H @ W2 + b2) ----------------
__global__ __launch_bounds__(256) void k_gemm2_norm(
    const float* __restrict__ W2, const float* __restrict__ b2)
{
    __shared__ float Hs[32][65];
    __shared__ float Ws[64][64];
    const int tok0 = blockIdx.x * 32;
    const int tid = threadIdx.x;
    const int tl = tid >> 3;
    const int cg = tid & 7;
    float acc[8];
    #pragma unroll
    for (int j = 0; j < 8; j++) acc[j] = 0.f;

    for (int k0 = 0; k0 < D; k0 += 64) {
        #pragma unroll
        for (int r = 0; r < 4; r++) {
            int f = tid + r * 256;
            int kk = f >> 4, c4 = (f & 15) << 2;
            *(float4*)&Ws[kk][c4] = *(const float4*)&W2[(size_t)(k0 + kk) * DC + c4];
        }
        #pragma unroll
        for (int r = 0; r < 2; r++) {
            int f = tid + r * 256;
            int m = f >> 4, c4 = (f & 15) << 2;
            float4 v = *(const float4*)&g_H[(size_t)(tok0 + m) * D + k0 + c4];
            Hs[m][c4] = v.x; Hs[m][c4 + 1] = v.y; Hs[m][c4 + 2] = v.z; Hs[m][c4 + 3] = v.w;
        }
        __syncthreads();
        #pragma unroll
        for (int kk = 0; kk < 64; kk++) {
            float h = Hs[tl][kk];
            float b[8];
            *(float4*)&b[0] = *(float4*)&Ws[kk][cg * 8];
            *(float4*)&b[4] = *(float4*)&Ws[kk][cg * 8 + 4];
            #pragma unroll
            for (int j = 0; j < 8; j++) acc[j] += h * b[j];
        }
        __syncthreads();
    }
    float ss = 0.f;
    #pragma unroll
    for (int j = 0; j < 8; j++) { acc[j] += b2[cg * 8 + j]; ss += acc[j] * acc[j]; }
    ss += __shfl_xor_sync(0xffffffffu, ss, 1);
    ss += __shfl_xor_sync(0xffffffffu, ss, 2);
    ss += __shfl_xor_sync(0xffffffffu, ss, 4);
    float inv = 1.0f / fmaxf(sqrtf(ss), 1e-12f);
    #pragma unroll
    for (int j = 0; j < 8; j++) acc[j] *= inv;
    *(float4*)&g_Ze[(size_t)(tok0 + tl) * DC + cg * 8]     = *(float4*)&acc[0];
    *(float4*)&g_Ze[(size_t)(tok0 + tl) * DC + cg * 8 + 4] = *(float4*)&acc[4];
}

// ---------------- kernel 2b: split Ze into bf16x3 ----------------
__global__ void k_split_ze()
{
    int i = blockIdx.x * 256 + threadIdx.x;
    split3(g_Ze[i], g_ZeSp0[i], g_ZeSp1[i], g_ZeSp2[i]);
}

// ---------------- kernel 3: sim + argmax via mma.sync bf16x6 ----------------
// CTA 256 thr / 8 warps; tile 128 tokens x 128 codes; K=64 (one chunk).
// Warp tile 64x32. smem 96KB -> 2 CTAs/SM.
#define SIM_SMEM 98304
__global__ __launch_bounds__(256, 2) void k_sim_mma()
{
    extern __shared__ char sm[];
    const uint32_t smb = smem_u32(sm);
    const int tid = threadIdx.x;
    const int lane = tid & 31, w = tid >> 5;
    const int tok0 = blockIdx.y * 128;
    const int cod0 = blockIdx.x * 128;
    const int wm = w & 1, wn = w >> 1;

    {
        const __nv_bfloat16* Ap[3] = { g_ZeSp0, g_ZeSp1, g_ZeSp2 };
        #pragma unroll
        for (int p = 0; p < 3; p++)
            #pragma unroll
            for (int it = 0; it < 4; it++) {
                int idx = tid + it * 256;            // 0..1023 = row*8 + chunk
                int r = idx >> 3, c = idx & 7;
                uint4 v = *(const uint4*)(Ap[p] + (size_t)(tok0 + r) * DC + c * 8);
                *(uint4*)(sm + p * 16384 + r * 128 + ((c ^ (r & 7)) << 4)) = v;
            }
        const __nv_bfloat16* Bp[3] = { g_ESp0, g_ESp1, g_ESp2 };
        #pragma unroll
        for (int p = 0; p < 3; p++)
            #pragma unroll
            for (int it = 0; it < 4; it++) {
                int idx = tid + it * 256;
                int r = idx >> 3, c = idx & 7;
                uint4 v = *(const uint4*)(Bp[p] + (size_t)(cod0 + r) * DC + c * 8);
                *(uint4*)(sm + 49152 + p * 16384 + r * 128 + ((c ^ (r & 7)) << 4)) = v;
            }
    }
    __syncthreads();

    float acc[4][4][4];
    #pragma unroll
    for (int mi = 0; mi < 4; mi++)
        #pragma unroll
        for (int ni = 0; ni < 4; ni++)
            #pragma unroll
            for (int f = 0; f < 4; f++) acc[mi][ni][f] = 0.f;

    const int l = lane & 7;
    const int sel = lane >> 3;
    const int pa[6] = {0, 0, 1, 1, 0, 2};
    const int pb[6] = {0, 1, 0, 1, 2, 0};

    #pragma unroll
    for (int pr = 0; pr < 6; pr++) {
        const uint32_t abase = smb + pa[pr] * 16384;
        const uint32_t bbase = smb + 49152 + pb[pr] * 16384;
        #pragma unroll
        for (int k16 = 0; k16 < 4; k16++) {
            uint32_t a[4][4];
            #pragma unroll
            for (int mi = 0; mi < 4; mi++) {
                int row = wm * 64 + mi * 16 + ((sel & 1) << 3) + l;
                int ch  = k16 * 2 + (sel >> 1);
                uint32_t addr = abase + row * 128 + ((ch ^ (row & 7)) << 4);
                LDSM4(a[mi][0], a[mi][1], a[mi][2], a[mi][3], addr);
            }
            #pragma unroll
            for (int p2 = 0; p2 < 2; p2++) {
                uint32_t b0, b1, b2, b3;
                int nrow = wn * 32 + (p2 * 2 + (sel >> 1)) * 8 + l;
                int ch = k16 * 2 + (sel & 1);
                uint32_t addr = bbase + nrow * 128 + ((ch ^ (nrow & 7)) << 4);
                LDSM4(b0, b1, b2, b3, addr);
                #pragma unroll
                for (int mi = 0; mi < 4; mi++) {
                    MMA16816(acc[mi][p2 * 2],     a[mi], b0, b1);
                    MMA16816(acc[mi][p2 * 2 + 1], a[mi], b2, b3);
                }
            }
        }
    }

    // ---- fused argmax epilogue ----
    const int gid = lane >> 2, tig = lane & 3;
    #pragma unroll
    for (int mi = 0; mi < 4; mi++)
        #pragma unroll
        for (int half = 0; half < 2; half++) {
            int token = tok0 + wm * 64 + mi * 16 + half * 8 + gid;
            float bv = -1e30f;
            int bc = 0;
            #pragma unroll
            for (int ni = 0; ni < 4; ni++) {         // ascending code order -> ties keep lowest
                int cb = cod0 + wn * 32 + ni * 8 + tig * 2;
                float v0 = acc[mi][ni][half * 2];
                float v1 = acc[mi][ni][half * 2 + 1];
                if (v0 > bv) { bv = v0; bc = cb; }
                if (v1 > bv) { bv = v1; bc = cb + 1; }
            }
            unsigned long long p =
                ((unsigned long long)fmap(bv) << 32) | (unsigned int)(KCODES - 1 - bc);
            unsigned long long q = __shfl_xor_sync(0xffffffffu, p, 1);
            if (q > p) p = q;
            q = __shfl_xor_sync(0xffffffffu, p, 2);
            if (q > p) p = q;
            if (tig == 0) atomicMax(&g_best[token], p);
        }
}

// ---------------- kernel 4: scatter one-hot ----------------
__global__ void k_scatter(float* __restrict__ codex)
{
    int t = blockIdx.x * 256 + threadIdx.x;
    if (t < N_TOK) {
        int c = KCODES - 1 - (int)(g_best[t] & 0xffffffffu);
        codex[(size_t)t * KCODES + c] = 1.0f;
    }
}

// ---------------- kernel 5: gather + loss partials + LayerNorm + out = y @ Wp + bp ----
__global__ __launch_bounds__(128) void k_ln_gemm3(
    const float* __restrict__ E, const float* __restrict__ gamma,
    const float* __restrict__ beta, const float* __restrict__ Wp,
    const float* __restrict__ bp, float* __restrict__ out)
{
    __shared__ float ys[64][16];
    __shared__ float sds[16];
    const int tok0 = blockIdx.x * 16;
    const int tid = threadIdx.x;
    const int tl = tid >> 3, cg = tid & 7;
    const int t = tok0 + tl;

    int code = KCODES - 1 - (int)(g_best[t] & 0xffffffffu);
    float q[8], z[8];
    *(float4*)&q[0] = *(const float4*)&E[(size_t)code * DC + cg * 8];
    *(float4*)&q[4] = *(const float4*)&E[(size_t)code * DC + cg * 8 + 4];
    *(float4*)&z[0] = *(const float4*)&g_Ze[(size_t)t * DC + cg * 8];
    *(float4*)&z[4] = *(const float4*)&g_Ze[(size_t)t * DC + cg * 8 + 4];

    float s = 0.f, s2 = 0.f, sd = 0.f;
    #pragma unroll
    for (int e = 0; e < 8; e++) {
        s += q[e]; s2 += q[e] * q[e];
        float d = q[e] - z[e]; sd += d * d;
    }
    #pragma unroll
    for (int w = 1; w < 8; w <<= 1) {
        s  += __shfl_xor_sync(0xffffffffu, s,  w);
        s2 += __shfl_xor_sync(0xffffffffu, s2, w);
        sd += __shfl_xor_sync(0xffffffffu, sd, w);
    }
    float mean = s * (1.0f / 64.0f);
    float var  = s2 * (1.0f / 64.0f) - mean * mean;
    float rstd = rsqrtf(var + 1e-5f);
    #pragma unroll
    for (int e = 0; e < 8; e++) {
        int c = cg * 8 + e;
        ys[c][tl] = (q[e] - mean) * rstd * gamma[c] + beta[c];
    }
    if (cg == 0) sds[tl] = sd;
    __syncthreads();
    if (tid == 0) {
        float tot = 0.f;
        #pragma unroll
        for (int i = 0; i < 16; i++) tot += sds[i];
        g_loss_part[blockIdx.x] = tot;
    }

    for (int n = tid; n < D; n += 128) {
        float acc[16];
        #pragma unroll
        for (int i = 0; i < 16; i++) acc[i] = 0.f;
        #pragma unroll 8
        for (int c = 0; c < DC; c++) {
            float w = Wp[(size_t)c * D + n];
            float4 y0 = *(float4*)&ys[c][0];
            float4 y1 = *(float4*)&ys[c][4];
            float4 y2 = *(float4*)&ys[c][8];
            float4 y3 = *(float4*)&ys[c][12];
            acc[0]  += y0.x * w; acc[1]  += y0.y * w; acc[2]  += y0.z * w; acc[3]  += y0.w * w;
            acc[4]  += y1.x * w; acc[5]  += y1.y * w; acc[6]  += y1.z * w; acc[7]  += y1.w * w;
            acc[8]  += y2.x * w; acc[9]  += y2.y * w; acc[10] += y2.z * w; acc[11] += y2.w * w;
            acc[12] += y3.x * w; acc[13] += y3.y * w; acc[14] += y3.z * w; acc[15] += y3.w * w;
        }
        float bb = bp[n];
        #pragma unroll
        for (int i = 0; i < 16; i++)
            out[(size_t)(tok0 + i) * D + n] = acc[i] + bb;
    }
}

// ---------------- kernel 6: deterministic loss reduction ----------------
__global__ void k_loss_reduce(float* __restrict__ loss_out)
{
    __shared__ float red[256];
    int tid = threadIdx.x;
    float s = 0.f;
    for (int i = tid; i < N_TOK / 16; i += 256) s += g_loss_part[i];
    red[tid] = s;
    __syncthreads();
    for (int w = 128; w > 0; w >>= 1) {
        if (tid < w) red[tid] += red[tid + w];
        __syncthreads();
    }
    if (tid == 0) loss_out[0] = red[0] * (1.0f / (float)(N_TOK * DC));
}

// ---------------- launch ----------------
extern "C" void kernel_launch(void* const* d_in, const int* in_sizes, int n_in,
                              void* d_out, int out_size)
{
    const float* Z   = (const float*)d_in[0];
    const float* W1  = (const float*)d_in[1];
    const float* b1  = (const float*)d_in[2];
    const float* W2  = (const float*)d_in[3];
    const float* b2  = (const float*)d_in[4];
    const float* emb = (const float*)d_in[5];
    const float* gam = (const float*)d_in[6];
    const float* bet = (const float*)d_in[7];
    const float* Wp  = (const float*)d_in[8];
    const float* bp  = (const float*)d_in[9];

    float* out   = (float*)d_out;
    float* lossp = out + (size_t)N_TOK * D;         // scalar after out (16B-aligned)
    float* codex = lossp + 1;                        // one-hot after loss

    (void)in_sizes; (void)n_in; (void)out_size;

    cudaFuncSetAttribute(k_gemm1_mma,
                         cudaFuncAttributeMaxDynamicSharedMemorySize, G1_SMEM);
    cudaFuncSetAttribute(k_sim_mma,
                         cudaFuncAttributeMaxDynamicSharedMemorySize, SIM_SMEM);

    k_split_in<<<(NZ + NW1 + NE) / 256, 256>>>(Z, W1, emb);
    k_gemm1_mma<<<dim3(D / 128, N_TOK / 128), 256, G1_SMEM>>>(b1, (float4*)lossp);
    k_gemm2_norm<<<N_TOK / 32, 256>>>(W2, b2);
    k_split_ze<<<(N_TOK * DC) / 256, 256>>>();
    k_sim_mma<<<dim3(KCODES / 128, N_TOK / 128), 256, SIM_SMEM>>>();
    k_scatter<<<(N_TOK + 255) / 256, 256>>>(codex);
    k_ln_gemm3<<<N_TOK / 16, 128>>>(emb, gam, bet, Wp, bp, out);
    k_loss_reduce<<<1, 256>>>(lossp);
}

// round 15
// speedup vs baseline: 1.1725x; 1.1725x over previous
#include <cuda_runtime.h>
#include <cuda_bf16.h>
#include <cstdint>
#include <math.h>

#define N_TOK 16384
#define D     768
#define DC    64
#define KCODES 8192

// ---------------- scratch (device globals: no runtime allocation) ----------------
__device__ float g_H[N_TOK * D];                 // tanh(Z@W1+b1), 48 MB
__device__ float g_Ze[N_TOK * DC];               // normalized encoder output, 4 MB
__device__ unsigned long long g_best[N_TOK];     // packed (mapped_sim<<32)|(8191-idx)
__device__ float g_loss_part[N_TOK / 16];        // per-block loss partials

// bf16 3-way exact splits (x = s0 + s1 + s2 + O(2^-27 x))
__device__ __align__(16) __nv_bfloat16 g_ZeSp0[N_TOK * DC];
__device__ __align__(16) __nv_bfloat16 g_ZeSp1[N_TOK * DC];
__device__ __align__(16) __nv_bfloat16 g_ZeSp2[N_TOK * DC];
__device__ __align__(16) __nv_bfloat16 g_ESp0[KCODES * DC];
__device__ __align__(16) __nv_bfloat16 g_ESp1[KCODES * DC];
__device__ __align__(16) __nv_bfloat16 g_ESp2[KCODES * DC];

// monotonic float->uint mapping (total order preserving)
__device__ __forceinline__ unsigned int fmap(float f) {
    unsigned int u = __float_as_uint(f);
    return (u & 0x80000000u) ? ~u : (u | 0x80000000u);
}

__device__ __forceinline__ uint32_t smem_u32(const void* p) {
    uint32_t a;
    asm("{ .reg .u64 t; cvta.to.shared.u64 t, %1; cvt.u32.u64 %0, t; }"
        : "=r"(a) : "l"(p));
    return a;
}

#define LDSM4(r0, r1, r2, r3, addr) \
    asm volatile("ldmatrix.sync.aligned.m8n8.x4.shared.b16 {%0,%1,%2,%3}, [%4];" \
                 : "=r"(r0), "=r"(r1), "=r"(r2), "=r"(r3) : "r"(addr))

#define MMA16816(c, a, b0, b1) \
    asm volatile("mma.sync.aligned.m16n8k16.row.col.f32.bf16.bf16.f32 " \
                 "{%0,%1,%2,%3}, {%4,%5,%6,%7}, {%8,%9}, {%0,%1,%2,%3};" \
                 : "+f"((c)[0]), "+f"((c)[1]), "+f"((c)[2]), "+f"((c)[3]) \
                 : "r"((a)[0]), "r"((a)[1]), "r"((a)[2]), "r"((a)[3]), \
                   "r"(b0), "r"(b1))

__device__ __forceinline__ void split3(float x, __nv_bfloat16& s0,
                                       __nv_bfloat16& s1, __nv_bfloat16& s2) {
    s0 = __float2bfloat16(x);
    float r1 = x - __bfloat162float(s0);
    s1 = __float2bfloat16(r1);
    s2 = __float2bfloat16(r1 - __bfloat162float(s1));
}

// ---------------- kernel 1: H = tanh(Z @ W1 + b1)  (+ zero loss+codex & g_best) ---
// R3/R13 proven fp32 version: BM=BN=128, BK=16, 256 threads, 8x8/thread.
__global__ __launch_bounds__(256, 2) void k_gemm1_tanh(
    const float* __restrict__ A, const float* __restrict__ B,
    const float* __restrict__ bias, float4* __restrict__ zero4)
{
    __shared__ float As[16][132];
    __shared__ float Bs[16][128];
    const int col0 = blockIdx.x * 128;
    const int row0 = blockIdx.y * 128;
    const int tid = threadIdx.x;
    const int tx = tid & 15, ty = tid >> 4;

    {
        const unsigned int flat = blockIdx.y * gridDim.x + blockIdx.x;   // 0..767
        const float4 z4 = make_float4(0.f, 0.f, 0.f, 0.f);
        const size_t total4 = ((size_t)N_TOK * KCODES + 1) / 4;
        const size_t stride = (size_t)768 * 256;
        for (size_t i = (size_t)flat * 256 + tid; i < total4; i += stride)
            zero4[i] = z4;
        if (flat == 0 && tid == 0)
            ((float*)zero4)[(size_t)N_TOK * KCODES] = 0.f;
        if (flat < 64) g_best[flat * 256 + tid] = 0ull;
    }

    float acc[8][8];
    #pragma unroll
    for (int i = 0; i < 8; i++)
        #pragma unroll
        for (int j = 0; j < 8; j++) acc[i][j] = 0.f;

    for (int k0 = 0; k0 < D; k0 += 16) {
        #pragma unroll
        for (int r = 0; r < 2; r++) {
            int f = tid + r * 256;
            int m = f >> 2;
            int c4 = (f & 3) << 2;
            float4 v = *(const float4*)&A[(size_t)(row0 + m) * D + k0 + c4];
            As[c4 + 0][m] = v.x; As[c4 + 1][m] = v.y;
            As[c4 + 2][m] = v.z; As[c4 + 3][m] = v.w;
        }
        #pragma unroll
        for (int r = 0; r < 2; r++) {
            int f = tid + r * 256;
            int kk = f >> 5;
            int c4 = (f & 31) << 2;
            *(float4*)&Bs[kk][c4] = *(const float4*)&B[(size_t)(k0 + kk) * D + col0 + c4];
        }
        __syncthreads();
        #pragma unroll
        for (int kk = 0; kk < 16; kk++) {
            float a[8];
            *(float4*)&a[0] = *(float4*)&As[kk][ty * 8];
            *(float4*)&a[4] = *(float4*)&As[kk][ty * 8 + 4];
            #pragma unroll
            for (int j4 = 0; j4 < 2; j4++) {
                float4 b = *(float4*)&Bs[kk][tx * 8 + j4 * 4];
                #pragma unroll
                for (int i = 0; i < 8; i++) {
                    acc[i][j4 * 4 + 0] += a[i] * b.x;
                    acc[i][j4 * 4 + 1] += a[i] * b.y;
                    acc[i][j4 * 4 + 2] += a[i] * b.z;
                    acc[i][j4 * 4 + 3] += a[i] * b.w;
                }
            }
        }
        __syncthreads();
    }
    #pragma unroll
    for (int i = 0; i < 8; i++) {
        int r = row0 + ty * 8 + i;
        #pragma unroll
        for (int j = 0; j < 8; j++)
            acc[i][j] = tanhf(acc[i][j] + bias[col0 + tx * 8 + j]);
        *(float4*)&g_H[(size_t)r * D + col0 + tx * 8]     = *(float4*)&acc[i][0];
        *(float4*)&g_H[(size_t)r * D + col0 + tx * 8 + 4] = *(float4*)&acc[i][4];
    }
}

// ---------------- kernel 2: Ze = l2norm(H @ W2 + b2)  (+ fused bf16x3 split) -------
__global__ __launch_bounds__(256) void k_gemm2_norm(
    const float* __restrict__ W2, const float* __restrict__ b2)
{
    __shared__ float Hs[32][65];
    __shared__ float Ws[64][64];
    const int tok0 = blockIdx.x * 32;
    const int tid = threadIdx.x;
    const int tl = tid >> 3;
    const int cg = tid & 7;
    float acc[8];
    #pragma unroll
    for (int j = 0; j < 8; j++) acc[j] = 0.f;

    for (int k0 = 0; k0 < D; k0 += 64) {
        #pragma unroll
        for (int r = 0; r < 4; r++) {
            int f = tid + r * 256;
            int kk = f >> 4, c4 = (f & 15) << 2;
            *(float4*)&Ws[kk][c4] = *(const float4*)&W2[(size_t)(k0 + kk) * DC + c4];
        }
        #pragma unroll
        for (int r = 0; r < 2; r++) {
            int f = tid + r * 256;
            int m = f >> 4, c4 = (f & 15) << 2;
            float4 v = *(const float4*)&g_H[(size_t)(tok0 + m) * D + k0 + c4];
            Hs[m][c4] = v.x; Hs[m][c4 + 1] = v.y; Hs[m][c4 + 2] = v.z; Hs[m][c4 + 3] = v.w;
        }
        __syncthreads();
        #pragma unroll
        for (int kk = 0; kk < 64; kk++) {
            float h = Hs[tl][kk];
            float b[8];
            *(float4*)&b[0] = *(float4*)&Ws[kk][cg * 8];
            *(float4*)&b[4] = *(float4*)&Ws[kk][cg * 8 + 4];
            #pragma unroll
            for (int j = 0; j < 8; j++) acc[j] += h * b[j];
        }
        __syncthreads();
    }
    float ss = 0.f;
    #pragma unroll
    for (int j = 0; j < 8; j++) { acc[j] += b2[cg * 8 + j]; ss += acc[j] * acc[j]; }
    ss += __shfl_xor_sync(0xffffffffu, ss, 1);
    ss += __shfl_xor_sync(0xffffffffu, ss, 2);
    ss += __shfl_xor_sync(0xffffffffu, ss, 4);
    float inv = 1.0f / fmaxf(sqrtf(ss), 1e-12f);
    #pragma unroll
    for (int j = 0; j < 8; j++) acc[j] *= inv;
    const size_t base = (size_t)(tok0 + tl) * DC + cg * 8;
    *(float4*)&g_Ze[base]     = *(float4*)&acc[0];
    *(float4*)&g_Ze[base + 4] = *(float4*)&acc[4];
    // fused bf16x3 split of Ze (values already in registers)
    __nv_bfloat16 s0[8], s1[8], s2[8];
    #pragma unroll
    for (int j = 0; j < 8; j++) split3(acc[j], s0[j], s1[j], s2[j]);
    *(uint4*)&g_ZeSp0[base] = *(uint4*)&s0[0];
    *(uint4*)&g_ZeSp1[base] = *(uint4*)&s1[0];
    *(uint4*)&g_ZeSp2[base] = *(uint4*)&s2[0];
}

// ---------------- kernel 2b: split emb into bf16x3 (small, one-time) --------------
__global__ void k_split_emb(const float* __restrict__ emb)
{
    int i = blockIdx.x * 256 + threadIdx.x;
    split3(emb[i], g_ESp0[i], g_ESp1[i], g_ESp2[i]);
}

// ---------------- kernel 3: sim + argmax via mma.sync bf16x6 ----------------
// CTA 256 thr / 8 warps; tile 128 tokens x 128 codes; K=64 (one chunk).
// Warp tile 64x32. smem 96KB -> 2 CTAs/SM.
#define SIM_SMEM 98304
__global__ __launch_bounds__(256, 2) void k_sim_mma()
{
    extern __shared__ char sm[];
    const uint32_t smb = smem_u32(sm);
    const int tid = threadIdx.x;
    const int lane = tid & 31, w = tid >> 5;
    const int tok0 = blockIdx.y * 128;
    const int cod0 = blockIdx.x * 128;
    const int wm = w & 1, wn = w >> 1;

    {
        const __nv_bfloat16* Ap[3] = { g_ZeSp0, g_ZeSp1, g_ZeSp2 };
        #pragma unroll
        for (int p = 0; p < 3; p++)
            #pragma unroll
            for (int it = 0; it < 4; it++) {
                int idx = tid + it * 256;            // 0..1023 = row*8 + chunk
                int r = idx >> 3, c = idx & 7;
                uint4 v = *(const uint4*)(Ap[p] + (size_t)(tok0 + r) * DC + c * 8);
                *(uint4*)(sm + p * 16384 + r * 128 + ((c ^ (r & 7)) << 4)) = v;
            }
        const __nv_bfloat16* Bp[3] = { g_ESp0, g_ESp1, g_ESp2 };
        #pragma unroll
        for (int p = 0; p < 3; p++)
            #pragma unroll
            for (int it = 0; it < 4; it++) {
                int idx = tid + it * 256;
                int r = idx >> 3, c = idx & 7;
                uint4 v = *(const uint4*)(Bp[p] + (size_t)(cod0 + r) * DC + c * 8);
                *(uint4*)(sm + 49152 + p * 16384 + r * 128 + ((c ^ (r & 7)) << 4)) = v;
            }
    }
    __syncthreads();

    float acc[4][4][4];
    #pragma unroll
    for (int mi = 0; mi < 4; mi++)
        #pragma unroll
        for (int ni = 0; ni < 4; ni++)
            #pragma unroll
            for (int f = 0; f < 4; f++) acc[mi][ni][f] = 0.f;

    const int l = lane & 7;
    const int sel = lane >> 3;
    const int pa[6] = {0, 0, 1, 1, 0, 2};
    const int pb[6] = {0, 1, 0, 1, 2, 0};

    #pragma unroll
    for (int pr = 0; pr < 6; pr++) {
        const uint32_t abase = smb + pa[pr] * 16384;
        const uint32_t bbase = smb + 49152 + pb[pr] * 16384;
        #pragma unroll
        for (int k16 = 0; k16 < 4; k16++) {
            uint32_t a[4][4];
            #pragma unroll
            for (int mi = 0; mi < 4; mi++) {
                int row = wm * 64 + mi * 16 + ((sel & 1) << 3) + l;
                int ch  = k16 * 2 + (sel >> 1);
                uint32_t addr = abase + row * 128 + ((ch ^ (row & 7)) << 4);
                LDSM4(a[mi][0], a[mi][1], a[mi][2], a[mi][3], addr);
            }
            #pragma unroll
            for (int p2 = 0; p2 < 2; p2++) {
                uint32_t b0, b1, b2, b3;
                int nrow = wn * 32 + (p2 * 2 + (sel >> 1)) * 8 + l;
                int ch = k16 * 2 + (sel & 1);
                uint32_t addr = bbase + nrow * 128 + ((ch ^ (nrow & 7)) << 4);
                LDSM4(b0, b1, b2, b3, addr);
                #pragma unroll
                for (int mi = 0; mi < 4; mi++) {
                    MMA16816(acc[mi][p2 * 2],     a[mi], b0, b1);
                    MMA16816(acc[mi][p2 * 2 + 1], a[mi], b2, b3);
                }
            }
        }
    }

    // ---- fused argmax epilogue ----
    const int gid = lane >> 2, tig = lane & 3;
    #pragma unroll
    for (int mi = 0; mi < 4; mi++)
        #pragma unroll
        for (int half = 0; half < 2; half++) {
            int token = tok0 + wm * 64 + mi * 16 + half * 8 + gid;
            float bv = -1e30f;
            int bc = 0;
            #pragma unroll
            for (int ni = 0; ni < 4; ni++) {         // ascending code order -> ties keep lowest
                int cb = cod0 + wn * 32 + ni * 8 + tig * 2;
                float v0 = acc[mi][ni][half * 2];
                float v1 = acc[mi][ni][half * 2 + 1];
                if (v0 > bv) { bv = v0; bc = cb; }
                if (v1 > bv) { bv = v1; bc = cb + 1; }
            }
            unsigned long long p =
                ((unsigned long long)fmap(bv) << 32) | (unsigned int)(KCODES - 1 - bc);
            unsigned long long q = __shfl_xor_sync(0xffffffffu, p, 1);
            if (q > p) p = q;
            q = __shfl_xor_sync(0xffffffffu, p, 2);
            if (q > p) p = q;
            if (tig == 0) atomicMax(&g_best[token], p);
        }
}

// ---------------- kernel 4: scatter one-hot ----------------
__global__ void k_scatter(float* __restrict__ codex)
{
    int t = blockIdx.x * 256 + threadIdx.x;
    if (t < N_TOK) {
        int c = KCODES - 1 - (int)(g_best[t] & 0xffffffffu);
        codex[(size_t)t * KCODES + c] = 1.0f;
    }
}

// ---------------- kernel 5: gather + loss partials + LayerNorm + out = y @ Wp + bp ----
__global__ __launch_bounds__(128) void k_ln_gemm3(
    const float* __restrict__ E, const float* __restrict__ gamma,
    const float* __restrict__ beta, const float* __restrict__ Wp,
    const float* __restrict__ bp, float* __restrict__ out)
{
    __shared__ float ys[64][16];
    __shared__ float sds[16];
    const int tok0 = blockIdx.x * 16;
    const int tid = threadIdx.x;
    const int tl = tid >> 3, cg = tid & 7;
    const int t = tok0 + tl;

    int code = KCODES - 1 - (int)(g_best[t] & 0xffffffffu);
    float q[8], z[8];
    *(float4*)&q[0] = *(const float4*)&E[(size_t)code * DC + cg * 8];
    *(float4*)&q[4] = *(const float4*)&E[(size_t)code * DC + cg * 8 + 4];
    *(float4*)&z[0] = *(const float4*)&g_Ze[(size_t)t * DC + cg * 8];
    *(float4*)&z[4] = *(const float4*)&g_Ze[(size_t)t * DC + cg * 8 + 4];

    float s = 0.f, s2 = 0.f, sd = 0.f;
    #pragma unroll
    for (int e = 0; e < 8; e++) {
        s += q[e]; s2 += q[e] * q[e];
        float d = q[e] - z[e]; sd += d * d;
    }
    #pragma unroll
    for (int w = 1; w < 8; w <<= 1) {
        s  += __shfl_xor_sync(0xffffffffu, s,  w);
        s2 += __shfl_xor_sync(0xffffffffu, s2, w);
        sd += __shfl_xor_sync(0xffffffffu, sd, w);
    }
    float mean = s * (1.0f / 64.0f);
    float var  = s2 * (1.0f / 64.0f) - mean * mean;
    float rstd = rsqrtf(var + 1e-5f);
    #pragma unroll
    for (int e = 0; e < 8; e++) {
        int c = cg * 8 + e;
        ys[c][tl] = (q[e] - mean) * rstd * gamma[c] + beta[c];
    }
    if (cg == 0) sds[tl] = sd;
    __syncthreads();
    if (tid == 0) {
        float tot = 0.f;
        #pragma unroll
        for (int i = 0; i < 16; i++) tot += sds[i];
        g_loss_part[blockIdx.x] = tot;
    }

    for (int n = tid; n < D; n += 128) {
        float acc[16];
        #pragma unroll
        for (int i = 0; i < 16; i++) acc[i] = 0.f;
        #pragma unroll 8
        for (int c = 0; c < DC; c++) {
            float w = Wp[(size_t)c * D + n];
            float4 y0 = *(float4*)&ys[c][0];
            float4 y1 = *(float4*)&ys[c][4];
            float4 y2 = *(float4*)&ys[c][8];
            float4 y3 = *(float4*)&ys[c][12];
            acc[0]  += y0.x * w; acc[1]  += y0.y * w; acc[2]  += y0.z * w; acc[3]  += y0.w * w;
            acc[4]  += y1.x * w; acc[5]  += y1.y * w; acc[6]  += y1.z * w; acc[7]  += y1.w * w;
            acc[8]  += y2.x * w; acc[9]  += y2.y * w; acc[10] += y2.z * w; acc[11] += y2.w * w;
            acc[12] += y3.x * w; acc[13] += y3.y * w; acc[14] += y3.z * w; acc[15] += y3.w * w;
        }
        float bb = bp[n];
        #pragma unroll
        for (int i = 0; i < 16; i++)
            out[(size_t)(tok0 + i) * D + n] = acc[i] + bb;
    }
}

// ---------------- kernel 6: deterministic loss reduction ----------------
__global__ void k_loss_reduce(float* __restrict__ loss_out)
{
    __shared__ float red[256];
    int tid = threadIdx.x;
    float s = 0.f;
    for (int i = tid; i < N_TOK / 16; i += 256) s += g_loss_part[i];
    red[tid] = s;
    __syncthreads();
    for (int w = 128; w > 0; w >>= 1) {
        if (tid < w) red[tid] += red[tid + w];
        __syncthreads();
    }
    if (tid == 0) loss_out[0] = red[0] * (1.0f / (float)(N_TOK * DC));
}

// ---------------- launch ----------------
extern "C" void kernel_launch(void* const* d_in, const int* in_sizes, int n_in,
                              void* d_out, int out_size)
{
    const float* Z   = (const float*)d_in[0];
    const float* W1  = (const float*)d_in[1];
    const float* b1  = (const float*)d_in[2];
    const float* W2  = (const float*)d_in[3];
    const float* b2  = (const float*)d_in[4];
    const float* emb = (const float*)d_in[5];
    const float* gam = (const float*)d_in[6];
    const float* bet = (const float*)d_in[7];
    const float* Wp  = (const float*)d_in[8];
    const float* bp  = (const float*)d_in[9];

    float* out   = (float*)d_out;
    float* lossp = out + (size_t)N_TOK * D;         // scalar after out (16B-aligned)
    float* codex = lossp + 1;                        // one-hot after loss

    (void)in_sizes; (void)n_in; (void)out_size;

    cudaFuncSetAttribute(k_sim_mma,
                         cudaFuncAttributeMaxDynamicSharedMemorySize, SIM_SMEM);

    k_split_emb<<<(KCODES * DC) / 256, 256>>>(emb);
    k_gemm1_tanh<<<dim3(D / 128, N_TOK / 128), 256>>>(Z, W1, b1, (float4*)lossp);
    k_gemm2_norm<<<N_TOK / 32, 256>>>(W2, b2);
    k_sim_mma<<<dim3(KCODES / 128, N_TOK / 128), 256, SIM_SMEM>>>();
    k_scatter<<<(N_TOK + 255) / 256, 256>>>(codex);
    k_ln_gemm3<<<N_TOK / 16, 128>>>(emb, gam, bet, Wp, bp, out);
    k_loss_reduce<<<1, 256>>>(lossp);
}

// round 16
// speedup vs baseline: 1.3206x; 1.1264x over previous
#include <cuda_runtime.h>
#include <cuda_bf16.h>
#include <cstdint>
#include <math.h>

#define N_TOK 16384
#define D     768
#define DC    64
#define KCODES 8192

// ---------------- scratch (device globals: no runtime allocation) ----------------
__device__ float g_H[N_TOK * D];                 // tanh(Z@W1+b1), 48 MB
__device__ float g_Ze[N_TOK * DC];               // normalized encoder output, 4 MB
__device__ unsigned long long g_best[N_TOK];     // packed (mapped_sim<<32)|(8191-idx)
__device__ float g_loss_part[N_TOK / 16];        // per-block loss partials

// bf16 3-way exact splits (x = s0 + s1 + s2 + O(2^-27 x))
__device__ __align__(16) __nv_bfloat16 g_ZeSp0[N_TOK * DC];
__device__ __align__(16) __nv_bfloat16 g_ZeSp1[N_TOK * DC];
__device__ __align__(16) __nv_bfloat16 g_ZeSp2[N_TOK * DC];
__device__ __align__(16) __nv_bfloat16 g_ESp0[KCODES * DC];
__device__ __align__(16) __nv_bfloat16 g_ESp1[KCODES * DC];
__device__ __align__(16) __nv_bfloat16 g_ESp2[KCODES * DC];

// monotonic float->uint mapping (total order preserving)
__device__ __forceinline__ unsigned int fmap(float f) {
    unsigned int u = __float_as_uint(f);
    return (u & 0x80000000u) ? ~u : (u | 0x80000000u);
}

__device__ __forceinline__ uint32_t smem_u32(const void* p) {
    uint32_t a;
    asm("{ .reg .u64 t; cvta.to.shared.u64 t, %1; cvt.u32.u64 %0, t; }"
        : "=r"(a) : "l"(p));
    return a;
}

#define LDSM4(r0, r1, r2, r3, addr) \
    asm volatile("ldmatrix.sync.aligned.m8n8.x4.shared.b16 {%0,%1,%2,%3}, [%4];" \
                 : "=r"(r0), "=r"(r1), "=r"(r2), "=r"(r3) : "r"(addr))

#define MMA16816(c, a, b0, b1) \
    asm volatile("mma.sync.aligned.m16n8k16.row.col.f32.bf16.bf16.f32 " \
                 "{%0,%1,%2,%3}, {%4,%5,%6,%7}, {%8,%9}, {%0,%1,%2,%3};" \
                 : "+f"((c)[0]), "+f"((c)[1]), "+f"((c)[2]), "+f"((c)[3]) \
                 : "r"((a)[0]), "r"((a)[1]), "r"((a)[2]), "r"((a)[3]), \
                   "r"(b0), "r"(b1))

__device__ __forceinline__ void split3(float x, __nv_bfloat16& s0,
                                       __nv_bfloat16& s1, __nv_bfloat16& s2) {
    s0 = __float2bfloat16(x);
    float r1 = x - __bfloat162float(s0);
    s1 = __float2bfloat16(r1);
    s2 = __float2bfloat16(r1 - __bfloat162float(s1));
}

// ---------------- kernel 1: H = tanh(Z @ W1 + b1)  (+ zero loss+codex & g_best) ---
// R3/R13 proven fp32 version: BM=BN=128, BK=16, 256 threads, 8x8/thread.
__global__ __launch_bounds__(256, 2) void k_gemm1_tanh(
    const float* __restrict__ A, const float* __restrict__ B,
    const float* __restrict__ bias, float4* __restrict__ zero4)
{
    __shared__ float As[16][132];
    __shared__ float Bs[16][128];
    const int col0 = blockIdx.x * 128;
    const int row0 = blockIdx.y * 128;
    const int tid = threadIdx.x;
    const int tx = tid & 15, ty = tid >> 4;

    {
        const unsigned int flat = blockIdx.y * gridDim.x + blockIdx.x;   // 0..767
        const float4 z4 = make_float4(0.f, 0.f, 0.f, 0.f);
        const size_t total4 = ((size_t)N_TOK * KCODES + 1) / 4;
        const size_t stride = (size_t)768 * 256;
        for (size_t i = (size_t)flat * 256 + tid; i < total4; i += stride)
            zero4[i] = z4;
        if (flat == 0 && tid == 0)
            ((float*)zero4)[(size_t)N_TOK * KCODES] = 0.f;
        if (flat < 64) g_best[flat * 256 + tid] = 0ull;
    }

    float acc[8][8];
    #pragma unroll
    for (int i = 0; i < 8; i++)
        #pragma unroll
        for (int j = 0; j < 8; j++) acc[i][j] = 0.f;

    for (int k0 = 0; k0 < D; k0 += 16) {
        #pragma unroll
        for (int r = 0; r < 2; r++) {
            int f = tid + r * 256;
            int m = f >> 2;
            int c4 = (f & 3) << 2;
            float4 v = *(const float4*)&A[(size_t)(row0 + m) * D + k0 + c4];
            As[c4 + 0][m] = v.x; As[c4 + 1][m] = v.y;
            As[c4 + 2][m] = v.z; As[c4 + 3][m] = v.w;
        }
        #pragma unroll
        for (int r = 0; r < 2; r++) {
            int f = tid + r * 256;
            int kk = f >> 5;
            int c4 = (f & 31) << 2;
            *(float4*)&Bs[kk][c4] = *(const float4*)&B[(size_t)(k0 + kk) * D + col0 + c4];
        }
        __syncthreads();
        #pragma unroll
        for (int kk = 0; kk < 16; kk++) {
            float a[8];
            *(float4*)&a[0] = *(float4*)&As[kk][ty * 8];
            *(float4*)&a[4] = *(float4*)&As[kk][ty * 8 + 4];
            #pragma unroll
            for (int j4 = 0; j4 < 2; j4++) {
                float4 b = *(float4*)&Bs[kk][tx * 8 + j4 * 4];
                #pragma unroll
                for (int i = 0; i < 8; i++) {
                    acc[i][j4 * 4 + 0] += a[i] * b.x;
                    acc[i][j4 * 4 + 1] += a[i] * b.y;
                    acc[i][j4 * 4 + 2] += a[i] * b.z;
                    acc[i][j4 * 4 + 3] += a[i] * b.w;
                }
            }
        }
        __syncthreads();
    }
    #pragma unroll
    for (int i = 0; i < 8; i++) {
        int r = row0 + ty * 8 + i;
        #pragma unroll
        for (int j = 0; j < 8; j++)
            acc[i][j] = tanhf(acc[i][j] + bias[col0 + tx * 8 + j]);
        *(float4*)&g_H[(size_t)r * D + col0 + tx * 8]     = *(float4*)&acc[i][0];
        *(float4*)&g_H[(size_t)r * D + col0 + tx * 8 + 4] = *(float4*)&acc[i][4];
    }
}

// ---------------- kernel 2: Ze = l2norm(H @ W2 + b2)  (+ fused bf16x3 split) -------
__global__ __launch_bounds__(256) void k_gemm2_norm(
    const float* __restrict__ W2, const float* __restrict__ b2)
{
    __shared__ float Hs[32][65];
    __shared__ float Ws[64][64];
    const int tok0 = blockIdx.x * 32;
    const int tid = threadIdx.x;
    const int tl = tid >> 3;
    const int cg = tid & 7;
    float acc[8];
    #pragma unroll
    for (int j = 0; j < 8; j++) acc[j] = 0.f;

    for (int k0 = 0; k0 < D; k0 += 64) {
        #pragma unroll
        for (int r = 0; r < 4; r++) {
            int f = tid + r * 256;
            int kk = f >> 4, c4 = (f & 15) << 2;
            *(float4*)&Ws[kk][c4] = *(const float4*)&W2[(size_t)(k0 + kk) * DC + c4];
        }
        #pragma unroll
        for (int r = 0; r < 2; r++) {
            int f = tid + r * 256;
            int m = f >> 4, c4 = (f & 15) << 2;
            float4 v = *(const float4*)&g_H[(size_t)(tok0 + m) * D + k0 + c4];
            Hs[m][c4] = v.x; Hs[m][c4 + 1] = v.y; Hs[m][c4 + 2] = v.z; Hs[m][c4 + 3] = v.w;
        }
        __syncthreads();
        #pragma unroll
        for (int kk = 0; kk < 64; kk++) {
            float h = Hs[tl][kk];
            float b[8];
            *(float4*)&b[0] = *(float4*)&Ws[kk][cg * 8];
            *(float4*)&b[4] = *(float4*)&Ws[kk][cg * 8 + 4];
            #pragma unroll
            for (int j = 0; j < 8; j++) acc[j] += h * b[j];
        }
        __syncthreads();
    }
    float ss = 0.f;
    #pragma unroll
    for (int j = 0; j < 8; j++) { acc[j] += b2[cg * 8 + j]; ss += acc[j] * acc[j]; }
    ss += __shfl_xor_sync(0xffffffffu, ss, 1);
    ss += __shfl_xor_sync(0xffffffffu, ss, 2);
    ss += __shfl_xor_sync(0xffffffffu, ss, 4);
    float inv = 1.0f / fmaxf(sqrtf(ss), 1e-12f);
    #pragma unroll
    for (int j = 0; j < 8; j++) acc[j] *= inv;
    const size_t base = (size_t)(tok0 + tl) * DC + cg * 8;
    *(float4*)&g_Ze[base]     = *(float4*)&acc[0];
    *(float4*)&g_Ze[base + 4] = *(float4*)&acc[4];
    // fused bf16x3 split of Ze (values already in registers)
    __nv_bfloat16 s0[8], s1[8], s2[8];
    #pragma unroll
    for (int j = 0; j < 8; j++) split3(acc[j], s0[j], s1[j], s2[j]);
    *(uint4*)&g_ZeSp0[base] = *(uint4*)&s0[0];
    *(uint4*)&g_ZeSp1[base] = *(uint4*)&s1[0];
    *(uint4*)&g_ZeSp2[base] = *(uint4*)&s2[0];
}

// ---------------- kernel 2b: split emb into bf16x3 (small, one-time) --------------
__global__ void k_split_emb(const float* __restrict__ emb)
{
    int i = blockIdx.x * 256 + threadIdx.x;
    split3(emb[i], g_ESp0[i], g_ESp1[i], g_ESp2[i]);
}

// ---------------- kernel 3: sim + argmax via mma.sync bf16x6 ----------------
// CTA 256 thr / 8 warps; tile 128 tokens x 256 codes; warp tile 64x64.
// k16-OUTER loop: A frags (3 planes) loaded once per k16, B frags once per
// B-plane; products grouped by B plane -> ldsm traffic halved vs R13.
// smem 144KB -> 1 CTA/SM.
#define SIM_SMEM 147456
__global__ __launch_bounds__(256, 1) void k_sim_mma()
{
    extern __shared__ char sm[];
    const uint32_t smb = smem_u32(sm);
    const int tid = threadIdx.x;
    const int lane = tid & 31, w = tid >> 5;
    const int tok0 = blockIdx.y * 128;
    const int cod0 = blockIdx.x * 256;
    const int wm = w & 1, wn = w >> 1;          // wn in 0..3

    {
        const __nv_bfloat16* Ap[3] = { g_ZeSp0, g_ZeSp1, g_ZeSp2 };
        #pragma unroll
        for (int p = 0; p < 3; p++)
            #pragma unroll
            for (int it = 0; it < 4; it++) {
                int idx = tid + it * 256;            // 0..1023 = row*8 + chunk
                int r = idx >> 3, c = idx & 7;
                uint4 v = *(const uint4*)(Ap[p] + (size_t)(tok0 + r) * DC + c * 8);
                *(uint4*)(sm + p * 16384 + r * 128 + ((c ^ (r & 7)) << 4)) = v;
            }
        const __nv_bfloat16* Bp[3] = { g_ESp0, g_ESp1, g_ESp2 };
        #pragma unroll
        for (int p = 0; p < 3; p++)
            #pragma unroll
            for (int it = 0; it < 8; it++) {
                int idx = tid + it * 256;            // 0..2047
                int r = idx >> 3, c = idx & 7;
                uint4 v = *(const uint4*)(Bp[p] + (size_t)(cod0 + r) * DC + c * 8);
                *(uint4*)(sm + 49152 + p * 32768 + r * 128 + ((c ^ (r & 7)) << 4)) = v;
            }
    }
    __syncthreads();

    float acc[4][8][4];
    #pragma unroll
    for (int mi = 0; mi < 4; mi++)
        #pragma unroll
        for (int ni = 0; ni < 8; ni++)
            #pragma unroll
            for (int f = 0; f < 4; f++) acc[mi][ni][f] = 0.f;

    const int l = lane & 7;
    const int sel = lane >> 3;

    #pragma unroll
    for (int k16 = 0; k16 < 4; k16++) {
        // ---- A fragments for all 3 planes, loaded once ----
        uint32_t a[3][4][4];
        {
            const int row = wm * 64 + ((sel & 1) << 3) + l;
            const int ch  = k16 * 2 + (sel >> 1);
            #pragma unroll
            for (int p = 0; p < 3; p++)
                #pragma unroll
                for (int mi = 0; mi < 4; mi++) {
                    int rr = row + mi * 16;
                    uint32_t addr = smb + p * 16384 + rr * 128 + ((ch ^ (rr & 7)) << 4);
                    LDSM4(a[p][mi][0], a[p][mi][1], a[p][mi][2], a[p][mi][3], addr);
                }
        }
        // ---- products grouped by B plane (B frags live briefly) ----
        // pb=0 -> pa {0,1,2}; pb=1 -> pa {0,1}; pb=2 -> pa {0}
        #pragma unroll
        for (int pb = 0; pb < 3; pb++) {
            uint32_t b[8][2];
            {
                const int ch = k16 * 2 + (sel & 1);
                #pragma unroll
                for (int p2 = 0; p2 < 4; p2++) {
                    int nrow = wn * 64 + (p2 * 2 + (sel >> 1)) * 8 + l;
                    uint32_t addr = smb + 49152 + pb * 32768
                                  + nrow * 128 + ((ch ^ (nrow & 7)) << 4);
                    LDSM4(b[p2 * 2][0], b[p2 * 2][1],
                          b[p2 * 2 + 1][0], b[p2 * 2 + 1][1], addr);
                }
            }
            const int npa = (pb == 0) ? 3 : (pb == 1) ? 2 : 1;
            #pragma unroll
            for (int pa = 0; pa < 3; pa++) {
                if (pa >= npa) break;
                #pragma unroll
                for (int mi = 0; mi < 4; mi++)
                    #pragma unroll
                    for (int ni = 0; ni < 8; ni++)
                        MMA16816(acc[mi][ni], a[pa][mi], b[ni][0], b[ni][1]);
            }
        }
    }

    // ---- fused argmax epilogue ----
    const int gid = lane >> 2, tig = lane & 3;
    #pragma unroll
    for (int mi = 0; mi < 4; mi++)
        #pragma unroll
        for (int half = 0; half < 2; half++) {
            int token = tok0 + wm * 64 + mi * 16 + half * 8 + gid;
            float bv = -1e30f;
            int bc = 0;
            #pragma unroll
            for (int ni = 0; ni < 8; ni++) {         // ascending code order -> ties keep lowest
                int cb = cod0 + wn * 64 + ni * 8 + tig * 2;
                float v0 = acc[mi][ni][half * 2];
                float v1 = acc[mi][ni][half * 2 + 1];
                if (v0 > bv) { bv = v0; bc = cb; }
                if (v1 > bv) { bv = v1; bc = cb + 1; }
            }
            unsigned long long p =
                ((unsigned long long)fmap(bv) << 32) | (unsigned int)(KCODES - 1 - bc);
            unsigned long long q = __shfl_xor_sync(0xffffffffu, p, 1);
            if (q > p) p = q;
            q = __shfl_xor_sync(0xffffffffu, p, 2);
            if (q > p) p = q;
            if (tig == 0) atomicMax(&g_best[token], p);
        }
}

// ---------------- kernel 4: scatter one-hot ----------------
__global__ void k_scatter(float* __restrict__ codex)
{
    int t = blockIdx.x * 256 + threadIdx.x;
    if (t < N_TOK) {
        int c = KCODES - 1 - (int)(g_best[t] & 0xffffffffu);
        codex[(size_t)t * KCODES + c] = 1.0f;
    }
}

// ---------------- kernel 5: gather + loss partials + LayerNorm + out = y @ Wp + bp ----
__global__ __launch_bounds__(128) void k_ln_gemm3(
    const float* __restrict__ E, const float* __restrict__ gamma,
    const float* __restrict__ beta, const float* __restrict__ Wp,
    const float* __restrict__ bp, float* __restrict__ out)
{
    __shared__ float ys[64][16];
    __shared__ float sds[16];
    const int tok0 = blockIdx.x * 16;
    const int tid = threadIdx.x;
    const int tl = tid >> 3, cg = tid & 7;
    const int t = tok0 + tl;

    int code = KCODES - 1 - (int)(g_best[t] & 0xffffffffu);
    float q[8], z[8];
    *(float4*)&q[0] = *(const float4*)&E[(size_t)code * DC + cg * 8];
    *(float4*)&q[4] = *(const float4*)&E[(size_t)code * DC + cg * 8 + 4];
    *(float4*)&z[0] = *(const float4*)&g_Ze[(size_t)t * DC + cg * 8];
    *(float4*)&z[4] = *(const float4*)&g_Ze[(size_t)t * DC + cg * 8 + 4];

    float s = 0.f, s2 = 0.f, sd = 0.f;
    #pragma unroll
    for (int e = 0; e < 8; e++) {
        s += q[e]; s2 += q[e] * q[e];
        float d = q[e] - z[e]; sd += d * d;
    }
    #pragma unroll
    for (int w = 1; w < 8; w <<= 1) {
        s  += __shfl_xor_sync(0xffffffffu, s,  w);
        s2 += __shfl_xor_sync(0xffffffffu, s2, w);
        sd += __shfl_xor_sync(0xffffffffu, sd, w);
    }
    float mean = s * (1.0f / 64.0f);
    float var  = s2 * (1.0f / 64.0f) - mean * mean;
    float rstd = rsqrtf(var + 1e-5f);
    #pragma unroll
    for (int e = 0; e < 8; e++) {
        int c = cg * 8 + e;
        ys[c][tl] = (q[e] - mean) * rstd * gamma[c] + beta[c];
    }
    if (cg == 0) sds[tl] = sd;
    __syncthreads();
    if (tid == 0) {
        float tot = 0.f;
        #pragma unroll
        for (int i = 0; i < 16; i++) tot += sds[i];
        g_loss_part[blockIdx.x] = tot;
    }

    for (int n = tid; n < D; n += 128) {
        float acc[16];
        #pragma unroll
        for (int i = 0; i < 16; i++) acc[i] = 0.f;
        #pragma unroll 8
        for (int c = 0; c < DC; c++) {
            float w = Wp[(size_t)c * D + n];
            float4 y0 = *(float4*)&ys[c][0];
            float4 y1 = *(float4*)&ys[c][4];
            float4 y2 = *(float4*)&ys[c][8];
            float4 y3 = *(float4*)&ys[c][12];
            acc[0]  += y0.x * w; acc[1]  += y0.y * w; acc[2]  += y0.z * w; acc[3]  += y0.w * w;
            acc[4]  += y1.x * w; acc[5]  += y1.y * w; acc[6]  += y1.z * w; acc[7]  += y1.w * w;
            acc[8]  += y2.x * w; acc[9]  += y2.y * w; acc[10] += y2.z * w; acc[11] += y2.w * w;
            acc[12] += y3.x * w; acc[13] += y3.y * w; acc[14] += y3.z * w; acc[15] += y3.w * w;
        }
        float bb = bp[n];
        #pragma unroll
        for (int i = 0; i < 16; i++)
            out[(size_t)(tok0 + i) * D + n] = acc[i] + bb;
    }
}

// ---------------- kernel 6: deterministic loss reduction ----------------
__global__ void k_loss_reduce(float* __restrict__ loss_out)
{
    __shared__ float red[256];
    int tid = threadIdx.x;
    float s = 0.f;
    for (int i = tid; i < N_TOK / 16; i += 256) s += g_loss_part[i];
    red[tid] = s;
    __syncthreads();
    for (int w = 128; w > 0; w >>= 1) {
        if (tid < w) red[tid] += red[tid + w];
        __syncthreads();
    }
    if (tid == 0) loss_out[0] = red[0] * (1.0f / (float)(N_TOK * DC));
}

// ---------------- launch ----------------
extern "C" void kernel_launch(void* const* d_in, const int* in_sizes, int n_in,
                              void* d_out, int out_size)
{
    const float* Z   = (const float*)d_in[0];
    const float* W1  = (const float*)d_in[1];
    const float* b1  = (const float*)d_in[2];
    const float* W2  = (const float*)d_in[3];
    const float* b2  = (const float*)d_in[4];
    const float* emb = (const float*)d_in[5];
    const float* gam = (const float*)d_in[6];
    const float* bet = (const float*)d_in[7];
    const float* Wp  = (const float*)d_in[8];
    const float* bp  = (const float*)d_in[9];

    float* out   = (float*)d_out;
    float* lossp = out + (size_t)N_TOK * D;         // scalar after out (16B-aligned)
    float* codex = lossp + 1;                        // one-hot after loss

    (void)in_sizes; (void)n_in; (void)out_size;

    cudaFuncSetAttribute(k_sim_mma,
                         cudaFuncAttributeMaxDynamicSharedMemorySize, SIM_SMEM);

    k_split_emb<<<(KCODES * DC) / 256, 256>>>(emb);
    k_gemm1_tanh<<<dim3(D / 128, N_TOK / 128), 256>>>(Z, W1, b1, (float4*)lossp);
    k_gemm2_norm<<<N_TOK / 32, 256>>>(W2, b2);
    k_sim_mma<<<dim3(KCODES / 256, N_TOK / 128), 256, SIM_SMEM>>>();
    k_scatter<<<(N_TOK + 255) / 256, 256>>>(codex);
    k_ln_gemm3<<<N_TOK / 16, 128>>>(emb, gam, bet, Wp, bp, out);
    k_loss_reduce<<<1, 256>>>(lossp);
}

// round 17
// speedup vs baseline: 1.4593x; 1.1050x over previous
#include <cuda_runtime.h>
#include <cuda_bf16.h>
#include <cstdint>
#include <math.h>

#define N_TOK 16384
#define D     768
#define DC    64
#define KCODES 8192

// ---------------- scratch (device globals: no runtime allocation) ----------------
__device__ float g_H[N_TOK * D];                 // tanh(Z@W1+b1), 48 MB
__device__ float g_Ze[N_TOK * DC];               // normalized encoder output, 4 MB
__device__ unsigned long long g_best[N_TOK];     // packed (mapped_sim<<32)|(8191-idx)
__device__ float g_loss_part[N_TOK / 16];        // per-block loss partials

// bf16 3-way exact splits (x = s0 + s1 + s2 + O(2^-27 x))
__device__ __align__(16) __nv_bfloat16 g_ZeSp0[N_TOK * DC];
__device__ __align__(16) __nv_bfloat16 g_ZeSp1[N_TOK * DC];
__device__ __align__(16) __nv_bfloat16 g_ZeSp2[N_TOK * DC];
__device__ __align__(16) __nv_bfloat16 g_ESp0[KCODES * DC];
__device__ __align__(16) __nv_bfloat16 g_ESp1[KCODES * DC];
__device__ __align__(16) __nv_bfloat16 g_ESp2[KCODES * DC];
// W1 transposed splits: [n][k], n,k in 0..767
__device__ __align__(16) __nv_bfloat16 g_W1TSp0[D * D];
__device__ __align__(16) __nv_bfloat16 g_W1TSp1[D * D];
__device__ __align__(16) __nv_bfloat16 g_W1TSp2[D * D];

// monotonic float->uint mapping (total order preserving)
__device__ __forceinline__ unsigned int fmap(float f) {
    unsigned int u = __float_as_uint(f);
    return (u & 0x80000000u) ? ~u : (u | 0x80000000u);
}

__device__ __forceinline__ uint32_t smem_u32(const void* p) {
    uint32_t a;
    asm("{ .reg .u64 t; cvta.to.shared.u64 t, %1; cvt.u32.u64 %0, t; }"
        : "=r"(a) : "l"(p));
    return a;
}

#define LDSM4(r0, r1, r2, r3, addr) \
    asm volatile("ldmatrix.sync.aligned.m8n8.x4.shared.b16 {%0,%1,%2,%3}, [%4];" \
                 : "=r"(r0), "=r"(r1), "=r"(r2), "=r"(r3) : "r"(addr))

#define MMA16816(c, a, b0, b1) \
    asm volatile("mma.sync.aligned.m16n8k16.row.col.f32.bf16.bf16.f32 " \
                 "{%0,%1,%2,%3}, {%4,%5,%6,%7}, {%8,%9}, {%0,%1,%2,%3};" \
                 : "+f"((c)[0]), "+f"((c)[1]), "+f"((c)[2]), "+f"((c)[3]) \
                 : "r"((a)[0]), "r"((a)[1]), "r"((a)[2]), "r"((a)[3]), \
                   "r"(b0), "r"(b1))

__device__ __forceinline__ void split3(float x, __nv_bfloat16& s0,
                                       __nv_bfloat16& s1, __nv_bfloat16& s2) {
    s0 = __float2bfloat16(x);
    float r1 = x - __bfloat162float(s0);
    s1 = __float2bfloat16(r1);
    s2 = __float2bfloat16(r1 - __bfloat162float(s1));
}

// ---------------- kernel 0: split emb + W1^T into bf16x3 planes ----------------
#define NE   (KCODES * DC)
#define NW1  (D * D)
__global__ void k_split_const(const float* __restrict__ emb,
                              const float* __restrict__ W1)
{
    int i = blockIdx.x * 256 + threadIdx.x;
    if (i < NE) {
        split3(emb[i], g_ESp0[i], g_ESp1[i], g_ESp2[i]);
    } else {
        int j = i - NE;
        if (j < NW1) {
            int n = j / D, k = j - n * D;      // j = n*768 + k (coalesced writes)
            split3(W1[(size_t)k * D + n], g_W1TSp0[j], g_W1TSp1[j], g_W1TSp2[j]);
        }
    }
}

// ---------------- kernel 1: H = tanh(Z @ W1 + b1) via mma bf16x6 ------------------
// R16-proven structure: tile 128 tokens x 256 cols, warp 64x64, k16-outer,
// B-plane grouping. Z split3 on the fly (no global Z split). 144KB smem.
// Also zeroes loss+codex output + g_best (fire-and-forget, DRAM idle here).
#define MMA_SMEM 147456
__global__ __launch_bounds__(256, 1) void k_gemm1_mma(
    const float* __restrict__ Z, const float* __restrict__ bias,
    float4* __restrict__ zero4)
{
    extern __shared__ char sm[];
    const uint32_t smb = smem_u32(sm);
    const int tid = threadIdx.x;
    const int lane = tid & 31, w = tid >> 5;
    const int tok0 = blockIdx.y * 128;
    const int col0 = blockIdx.x * 256;
    const int wm = w & 1, wn = w >> 1;          // wn in 0..3

    // ---- fire-and-forget zeroing of loss + one-hot output + g_best ----
    {
        const unsigned int flat = blockIdx.y * gridDim.x + blockIdx.x;   // 0..383
        const float4 z4 = make_float4(0.f, 0.f, 0.f, 0.f);
        const size_t total4 = ((size_t)N_TOK * KCODES + 1) / 4;
        const size_t stride = (size_t)384 * 256;
        for (size_t i = (size_t)flat * 256 + tid; i < total4; i += stride)
            zero4[i] = z4;
        if (flat == 0 && tid == 0)
            ((float*)zero4)[(size_t)N_TOK * KCODES] = 0.f;
        if (flat < 64) g_best[flat * 256 + tid] = 0ull;
    }

    float acc[4][8][4];
    #pragma unroll
    for (int mi = 0; mi < 4; mi++)
        #pragma unroll
        for (int ni = 0; ni < 8; ni++)
            #pragma unroll
            for (int f = 0; f < 4; f++) acc[mi][ni][f] = 0.f;

    const int l = lane & 7;
    const int sel = lane >> 3;

    const __nv_bfloat16* Bp[3] = { g_W1TSp0, g_W1TSp1, g_W1TSp2 };

    for (int kc0 = 0; kc0 < D; kc0 += 64) {
        // ---- A tile: load Z fp32, split3 in registers, write 3 bf16 planes ----
        #pragma unroll
        for (int it = 0; it < 4; it++) {
            int idx = tid + it * 256;               // 0..1023 = row*8 + chunk
            int r = idx >> 3, c = idx & 7;
            float f[8];
            *(float4*)&f[0] = *(const float4*)&Z[(size_t)(tok0 + r) * D + kc0 + c * 8];
            *(float4*)&f[4] = *(const float4*)&Z[(size_t)(tok0 + r) * D + kc0 + c * 8 + 4];
            __nv_bfloat16 s0[8], s1[8], s2[8];
            #pragma unroll
            for (int j = 0; j < 8; j++) split3(f[j], s0[j], s1[j], s2[j]);
            uint32_t off = r * 128 + ((c ^ (r & 7)) << 4);
            *(uint4*)(sm + off)             = *(uint4*)&s0[0];
            *(uint4*)(sm + 16384 + off)     = *(uint4*)&s1[0];
            *(uint4*)(sm + 32768 + off)     = *(uint4*)&s2[0];
        }
        // ---- B tile: 3 pre-split W1T planes, 256 rows x 64 k ----
        #pragma unroll
        for (int p = 0; p < 3; p++)
            #pragma unroll
            for (int it = 0; it < 8; it++) {
                int idx = tid + it * 256;           // 0..2047
                int r = idx >> 3, c = idx & 7;
                uint4 v = *(const uint4*)(Bp[p] + (size_t)(col0 + r) * D + kc0 + c * 8);
                *(uint4*)(sm + 49152 + p * 32768 + r * 128 + ((c ^ (r & 7)) << 4)) = v;
            }
        __syncthreads();

        #pragma unroll
        for (int k16 = 0; k16 < 4; k16++) {
            // A fragments for all 3 planes, loaded once
            uint32_t a[3][4][4];
            {
                const int row = wm * 64 + ((sel & 1) << 3) + l;
                const int ch  = k16 * 2 + (sel >> 1);
                #pragma unroll
                for (int p = 0; p < 3; p++)
                    #pragma unroll
                    for (int mi = 0; mi < 4; mi++) {
                        int rr = row + mi * 16;
                        uint32_t addr = smb + p * 16384 + rr * 128 + ((ch ^ (rr & 7)) << 4);
                        LDSM4(a[p][mi][0], a[p][mi][1], a[p][mi][2], a[p][mi][3], addr);
                    }
            }
            // products grouped by B plane: pb=0 -> pa{0,1,2}; pb=1 -> {0,1}; pb=2 -> {0}
            #pragma unroll
            for (int pb = 0; pb < 3; pb++) {
                uint32_t b[8][2];
                {
                    const int ch = k16 * 2 + (sel & 1);
                    #pragma unroll
                    for (int p2 = 0; p2 < 4; p2++) {
                        int nrow = wn * 64 + (p2 * 2 + (sel >> 1)) * 8 + l;
                        uint32_t addr = smb + 49152 + pb * 32768
                                      + nrow * 128 + ((ch ^ (nrow & 7)) << 4);
                        LDSM4(b[p2 * 2][0], b[p2 * 2][1],
                              b[p2 * 2 + 1][0], b[p2 * 2 + 1][1], addr);
                    }
                }
                const int npa = (pb == 0) ? 3 : (pb == 1) ? 2 : 1;
                #pragma unroll
                for (int pa = 0; pa < 3; pa++) {
                    if (pa >= npa) break;
                    #pragma unroll
                    for (int mi = 0; mi < 4; mi++)
                        #pragma unroll
                        for (int ni = 0; ni < 8; ni++)
                            MMA16816(acc[mi][ni], a[pa][mi], b[ni][0], b[ni][1]);
                }
            }
        }
        __syncthreads();
    }

    // ---- epilogue: + bias, tanh, store fp32 H ----
    const int gid = lane >> 2, tig = lane & 3;
    float2 bb[8];
    #pragma unroll
    for (int ni = 0; ni < 8; ni++)
        bb[ni] = *(const float2*)&bias[col0 + wn * 64 + ni * 8 + tig * 2];
    #pragma unroll
    for (int mi = 0; mi < 4; mi++)
        #pragma unroll
        for (int half = 0; half < 2; half++) {
            int token = tok0 + wm * 64 + mi * 16 + half * 8 + gid;
            #pragma unroll
            for (int ni = 0; ni < 8; ni++) {
                int col = col0 + wn * 64 + ni * 8 + tig * 2;
                float2 o;
                o.x = tanhf(acc[mi][ni][half * 2]     + bb[ni].x);
                o.y = tanhf(acc[mi][ni][half * 2 + 1] + bb[ni].y);
                *(float2*)&g_H[(size_t)token * D + col] = o;
            }
        }
}

// ---------------- kernel 2: Ze = l2norm(H @ W2 + b2)  (+ fused bf16x3 split) -------
__global__ __launch_bounds__(256) void k_gemm2_norm(
    const float* __restrict__ W2, const float* __restrict__ b2)
{
    __shared__ float Hs[32][65];
    __shared__ float Ws[64][64];
    const int tok0 = blockIdx.x * 32;
    const int tid = threadIdx.x;
    const int tl = tid >> 3;
    const int cg = tid & 7;
    float acc[8];
    #pragma unroll
    for (int j = 0; j < 8; j++) acc[j] = 0.f;

    for (int k0 = 0; k0 < D; k0 += 64) {
        #pragma unroll
        for (int r = 0; r < 4; r++) {
            int f = tid + r * 256;
            int kk = f >> 4, c4 = (f & 15) << 2;
            *(float4*)&Ws[kk][c4] = *(const float4*)&W2[(size_t)(k0 + kk) * DC + c4];
        }
        #pragma unroll
        for (int r = 0; r < 2; r++) {
            int f = tid + r * 256;
            int m = f >> 4, c4 = (f & 15) << 2;
            float4 v = *(const float4*)&g_H[(size_t)(tok0 + m) * D + k0 + c4];
            Hs[m][c4] = v.x; Hs[m][c4 + 1] = v.y; Hs[m][c4 + 2] = v.z; Hs[m][c4 + 3] = v.w;
        }
        __syncthreads();
        #pragma unroll
        for (int kk = 0; kk < 64; kk++) {
            float h = Hs[tl][kk];
            float b[8];
            *(float4*)&b[0] = *(float4*)&Ws[kk][cg * 8];
            *(float4*)&b[4] = *(float4*)&Ws[kk][cg * 8 + 4];
            #pragma unroll
            for (int j = 0; j < 8; j++) acc[j] += h * b[j];
        }
        __syncthreads();
    }
    float ss = 0.f;
    #pragma unroll
    for (int j = 0; j < 8; j++) { acc[j] += b2[cg * 8 + j]; ss += acc[j] * acc[j]; }
    ss += __shfl_xor_sync(0xffffffffu, ss, 1);
    ss += __shfl_xor_sync(0xffffffffu, ss, 2);
    ss += __shfl_xor_sync(0xffffffffu, ss, 4);
    float inv = 1.0f / fmaxf(sqrtf(ss), 1e-12f);
    #pragma unroll
    for (int j = 0; j < 8; j++) acc[j] *= inv;
    const size_t base = (size_t)(tok0 + tl) * DC + cg * 8;
    *(float4*)&g_Ze[base]     = *(float4*)&acc[0];
    *(float4*)&g_Ze[base + 4] = *(float4*)&acc[4];
    // fused bf16x3 split of Ze (values already in registers)
    __nv_bfloat16 s0[8], s1[8], s2[8];
    #pragma unroll
    for (int j = 0; j < 8; j++) split3(acc[j], s0[j], s1[j], s2[j]);
    *(uint4*)&g_ZeSp0[base] = *(uint4*)&s0[0];
    *(uint4*)&g_ZeSp1[base] = *(uint4*)&s1[0];
    *(uint4*)&g_ZeSp2[base] = *(uint4*)&s2[0];
}

// ---------------- kernel 3: sim + argmax via mma.sync bf16x6 (R16 proven) ---------
// CTA 256 thr / 8 warps; tile 128 tokens x 256 codes; warp 64x64; k16-outer,
// B-plane grouping; smem 144KB -> 1 CTA/SM.
#define SIM_SMEM 147456
__global__ __launch_bounds__(256, 1) void k_sim_mma()
{
    extern __shared__ char sm[];
    const uint32_t smb = smem_u32(sm);
    const int tid = threadIdx.x;
    const int lane = tid & 31, w = tid >> 5;
    const int tok0 = blockIdx.y * 128;
    const int cod0 = blockIdx.x * 256;
    const int wm = w & 1, wn = w >> 1;          // wn in 0..3

    {
        const __nv_bfloat16* Ap[3] = { g_ZeSp0, g_ZeSp1, g_ZeSp2 };
        #pragma unroll
        for (int p = 0; p < 3; p++)
            #pragma unroll
            for (int it = 0; it < 4; it++) {
                int idx = tid + it * 256;            // 0..1023 = row*8 + chunk
                int r = idx >> 3, c = idx & 7;
                uint4 v = *(const uint4*)(Ap[p] + (size_t)(tok0 + r) * DC + c * 8);
                *(uint4*)(sm + p * 16384 + r * 128 + ((c ^ (r & 7)) << 4)) = v;
            }
        const __nv_bfloat16* Bp[3] = { g_ESp0, g_ESp1, g_ESp2 };
        #pragma unroll
        for (int p = 0; p < 3; p++)
            #pragma unroll
            for (int it = 0; it < 8; it++) {
                int idx = tid + it * 256;            // 0..2047
                int r = idx >> 3, c = idx & 7;
                uint4 v = *(const uint4*)(Bp[p] + (size_t)(cod0 + r) * DC + c * 8);
                *(uint4*)(sm + 49152 + p * 32768 + r * 128 + ((c ^ (r & 7)) << 4)) = v;
            }
    }
    __syncthreads();

    float acc[4][8][4];
    #pragma unroll
    for (int mi = 0; mi < 4; mi++)
        #pragma unroll
        for (int ni = 0; ni < 8; ni++)
            #pragma unroll
            for (int f = 0; f < 4; f++) acc[mi][ni][f] = 0.f;

    const int l = lane & 7;
    const int sel = lane >> 3;

    #pragma unroll
    for (int k16 = 0; k16 < 4; k16++) {
        uint32_t a[3][4][4];
        {
            const int row = wm * 64 + ((sel & 1) << 3) + l;
            const int ch  = k16 * 2 + (sel >> 1);
            #pragma unroll
            for (int p = 0; p < 3; p++)
                #pragma unroll
                for (int mi = 0; mi < 4; mi++) {
                    int rr = row + mi * 16;
                    uint32_t addr = smb + p * 16384 + rr * 128 + ((ch ^ (rr & 7)) << 4);
                    LDSM4(a[p][mi][0], a[p][mi][1], a[p][mi][2], a[p][mi][3], addr);
                }
        }
        #pragma unroll
        for (int pb = 0; pb < 3; pb++) {
            uint32_t b[8][2];
            {
                const int ch = k16 * 2 + (sel & 1);
                #pragma unroll
                for (int p2 = 0; p2 < 4; p2++) {
                    int nrow = wn * 64 + (p2 * 2 + (sel >> 1)) * 8 + l;
                    uint32_t addr = smb + 49152 + pb * 32768
                                  + nrow * 128 + ((ch ^ (nrow & 7)) << 4);
                    LDSM4(b[p2 * 2][0], b[p2 * 2][1],
                          b[p2 * 2 + 1][0], b[p2 * 2 + 1][1], addr);
                }
            }
            const int npa = (pb == 0) ? 3 : (pb == 1) ? 2 : 1;
            #pragma unroll
            for (int pa = 0; pa < 3; pa++) {
                if (pa >= npa) break;
                #pragma unroll
                for (int mi = 0; mi < 4; mi++)
                    #pragma unroll
                    for (int ni = 0; ni < 8; ni++)
                        MMA16816(acc[mi][ni], a[pa][mi], b[ni][0], b[ni][1]);
            }
        }
    }

    // ---- fused argmax epilogue ----
    const int gid = lane >> 2, tig = lane & 3;
    #pragma unroll
    for (int mi = 0; mi < 4; mi++)
        #pragma unroll
        for (int half = 0; half < 2; half++) {
            int token = tok0 + wm * 64 + mi * 16 + half * 8 + gid;
            float bv = -1e30f;
            int bc = 0;
            #pragma unroll
            for (int ni = 0; ni < 8; ni++) {         // ascending code order -> ties keep lowest
                int cb = cod0 + wn * 64 + ni * 8 + tig * 2;
                float v0 = acc[mi][ni][half * 2];
                float v1 = acc[mi][ni][half * 2 + 1];
                if (v0 > bv) { bv = v0; bc = cb; }
                if (v1 > bv) { bv = v1; bc = cb + 1; }
            }
            unsigned long long p =
                ((unsigned long long)fmap(bv) << 32) | (unsigned int)(KCODES - 1 - bc);
            unsigned long long q = __shfl_xor_sync(0xffffffffu, p, 1);
            if (q > p) p = q;
            q = __shfl_xor_sync(0xffffffffu, p, 2);
            if (q > p) p = q;
            if (tig == 0) atomicMax(&g_best[token], p);
        }
}

// ---------------- kernel 4: scatter one-hot ----------------
__global__ void k_scatter(float* __restrict__ codex)
{
    int t = blockIdx.x * 256 + threadIdx.x;
    if (t < N_TOK) {
        int c = KCODES - 1 - (int)(g_best[t] & 0xffffffffu);
        codex[(size_t)t * KCODES + c] = 1.0f;
    }
}

// ---------------- kernel 5: gather + loss partials + LayerNorm + out = y @ Wp + bp ----
__global__ __launch_bounds__(128) void k_ln_gemm3(
    const float* __restrict__ E, const float* __restrict__ gamma,
    const float* __restrict__ beta, const float* __restrict__ Wp,
    const float* __restrict__ bp, float* __restrict__ out)
{
    __shared__ float ys[64][16];
    __shared__ float sds[16];
    const int tok0 = blockIdx.x * 16;
    const int tid = threadIdx.x;
    const int tl = tid >> 3, cg = tid & 7;
    const int t = tok0 + tl;

    int code = KCODES - 1 - (int)(g_best[t] & 0xffffffffu);
    float q[8], z[8];
    *(float4*)&q[0] = *(const float4*)&E[(size_t)code * DC + cg * 8];
    *(float4*)&q[4] = *(const float4*)&E[(size_t)code * DC + cg * 8 + 4];
    *(float4*)&z[0] = *(const float4*)&g_Ze[(size_t)t * DC + cg * 8];
    *(float4*)&z[4] = *(const float4*)&g_Ze[(size_t)t * DC + cg * 8 + 4];

    float s = 0.f, s2 = 0.f, sd = 0.f;
    #pragma unroll
    for (int e = 0; e < 8; e++) {
        s += q[e]; s2 += q[e] * q[e];
        float d = q[e] - z[e]; sd += d * d;
    }
    #pragma unroll
    for (int w = 1; w < 8; w <<= 1) {
        s  += __shfl_xor_sync(0xffffffffu, s,  w);
        s2 += __shfl_xor_sync(0xffffffffu, s2, w);
        sd += __shfl_xor_sync(0xffffffffu, sd, w);
    }
    float mean = s * (1.0f / 64.0f);
    float var  = s2 * (1.0f / 64.0f) - mean * mean;
    float rstd = rsqrtf(var + 1e-5f);
    #pragma unroll
    for (int e = 0; e < 8; e++) {
        int c = cg * 8 + e;
        ys[c][tl] = (q[e] - mean) * rstd * gamma[c] + beta[c];
    }
    if (cg == 0) sds[tl] = sd;
    __syncthreads();
    if (tid == 0) {
        float tot = 0.f;
        #pragma unroll
        for (int i = 0; i < 16; i++) tot += sds[i];
        g_loss_part[blockIdx.x] = tot;
    }

    for (int n = tid; n < D; n += 128) {
        float acc[16];
        #pragma unroll
        for (int i = 0; i < 16; i++) acc[i] = 0.f;
        #pragma unroll 8
        for (int c = 0; c < DC; c++) {
            float w = Wp[(size_t)c * D + n];
            float4 y0 = *(float4*)&ys[c][0];
            float4 y1 = *(float4*)&ys[c][4];
            float4 y2 = *(float4*)&ys[c][8];
            float4 y3 = *(float4*)&ys[c][12];
            acc[0]  += y0.x * w; acc[1]  += y0.y * w; acc[2]  += y0.z * w; acc[3]  += y0.w * w;
            acc[4]  += y1.x * w; acc[5]  += y1.y * w; acc[6]  += y1.z * w; acc[7]  += y1.w * w;
            acc[8]  += y2.x * w; acc[9]  += y2.y * w; acc[10] += y2.z * w; acc[11] += y2.w * w;
            acc[12] += y3.x * w; acc[13] += y3.y * w; acc[14] += y3.z * w; acc[15] += y3.w * w;
        }
        float bb = bp[n];
        #pragma unroll
        for (int i = 0; i < 16; i++)
            out[(size_t)(tok0 + i) * D + n] = acc[i] + bb;
    }
}

// ---------------- kernel 6: deterministic loss reduction ----------------
__global__ void k_loss_reduce(float* __restrict__ loss_out)
{
    __shared__ float red[256];
    int tid = threadIdx.x;
    float s = 0.f;
    for (int i = tid; i < N_TOK / 16; i += 256) s += g_loss_part[i];
    red[tid] = s;
    __syncthreads();
    for (int w = 128; w > 0; w >>= 1) {
        if (tid < w) red[tid] += red[tid + w];
        __syncthreads();
    }
    if (tid == 0) loss_out[0] = red[0] * (1.0f / (float)(N_TOK * DC));
}

// ---------------- launch ----------------
extern "C" void kernel_launch(void* const* d_in, const int* in_sizes, int n_in,
                              void* d_out, int out_size)
{
    const float* Z   = (const float*)d_in[0];
    const float* W1  = (const float*)d_in[1];
    const float* b1  = (const float*)d_in[2];
    const float* W2  = (const float*)d_in[3];
    const float* b2  = (const float*)d_in[4];
    const float* emb = (const float*)d_in[5];
    const float* gam = (const float*)d_in[6];
    const float* bet = (const float*)d_in[7];
    const float* Wp  = (const float*)d_in[8];
    const float* bp  = (const float*)d_in[9];

    float* out   = (float*)d_out;
    float* lossp = out + (size_t)N_TOK * D;         // scalar after out (16B-aligned)
    float* codex = lossp + 1;                        // one-hot after loss

    (void)in_sizes; (void)n_in; (void)out_size;

    cudaFuncSetAttribute(k_gemm1_mma,
                         cudaFuncAttributeMaxDynamicSharedMemorySize, MMA_SMEM);
    cudaFuncSetAttribute(k_sim_mma,
                         cudaFuncAttributeMaxDynamicSharedMemorySize, SIM_SMEM);

    k_split_const<<<(NE + NW1 + 255) / 256, 256>>>(emb, W1);
    k_gemm1_mma<<<dim3(D / 256, N_TOK / 128), 256, MMA_SMEM>>>(Z, b1, (float4*)lossp);
    k_gemm2_norm<<<N_TOK / 32, 256>>>(W2, b2);
    k_sim_mma<<<dim3(KCODES / 256, N_TOK / 128), 256, SIM_SMEM>>>();
    k_scatter<<<(N_TOK + 255) / 256, 256>>>(codex);
    k_ln_gemm3<<<N_TOK / 16, 128>>>(emb, gam, bet, Wp, bp, out);
    k_loss_reduce<<<1, 256>>>(lossp);
}